// round 16
// baseline (speedup 1.0000x reference)
#include <cuda_runtime.h>
#include <cuda_fp16.h>
#include <cstdint>

#define NB 32
#define NS 8
#define NHD 8
#define QKIN 8192
#define TKD 512
#define DKH 64
#define KSLICES 64
#define KSLEN 128

typedef unsigned long long u64;
typedef unsigned int u32;

// ---- scratch (static __device__ globals; no allocations) ----
__device__ float g_qa[NB * QKIN];
__device__ float g_ka[NB * NS * QKIN];
__device__ float g_qpart[KSLICES * NB * TKD];
__device__ float g_q[NB * TKD];
__device__ float g_p[NB * NHD * QKIN];
__device__ float g_wgt[NB * NHD * NS];
__device__ __half g_vsh[NB * 1024 * 128];            // weighted V (own head), half
__device__ __half g_vhh[NB * NHD * 2 * 32 * 128];    // halo rows (consumer-head weighted)
__device__ __half g_xh[NB * 1024 * 128];             // conv_v output, half
__device__ uint2 g_wBv[9 * 16 * 8 * 32];             // fp16 B frags conv_v
__device__ uint2 g_wBo[9 * 8 * 8 * 32];              // fp16 B frags conv_o

__constant__ int c_ridx[8] = {0, 0, 0, 0, 0, 1, 2, 3};

__device__ __forceinline__ u32 h2(float a, float b) {
    __half2 v = __float22half2_rn(make_float2(a, b));
    return *(u32*)&v;
}

__device__ __forceinline__ u32 smem_u32(const void* p) {
    u32 a;
    asm("{ .reg .u64 t; cvta.to.shared.u64 t, %1; cvt.u32.u64 %0, t; }" : "=r"(a) : "l"(p));
    return a;
}

#define CPA16(dst, src) \
    asm volatile("cp.async.ca.shared.global [%0], [%1], 16;" :: "r"(dst), "l"(src))

__device__ __forceinline__ void mma_f16(float4& d, const u32* a, uint2 b) {
    asm volatile("mma.sync.aligned.m16n8k16.row.col.f32.f16.f16.f32 "
        "{%0,%1,%2,%3}, {%4,%5,%6,%7}, {%8,%9}, {%0,%1,%2,%3};"
        : "+f"(d.x), "+f"(d.y), "+f"(d.z), "+f"(d.w)
        : "r"(a[0]), "r"(a[1]), "r"(a[2]), "r"(a[3]), "r"(b.x), "r"(b.y));
}

// ======================= pool =======================
__global__ void pool_kernel(const float* __restrict__ in, int nImg, int which) {
    float* out = which ? g_ka : g_qa;
    int idx = blockIdx.x * 256 + threadIdx.x;
    if (idx >= nImg * 2048) return;
    int c4 = idx & 31;
    int pw = (idx >> 5) & 7;
    int ph = (idx >> 8) & 7;
    int img = idx >> 11;
    const float4* p4 = (const float4*)in;
    float sx = 0.f, sy = 0.f, sz = 0.f, sw = 0.f;
#pragma unroll
    for (int i = 0; i < 4; i++)
#pragma unroll
        for (int j = 0; j < 4; j++) {
            float4 v = p4[((img * 32 + ph * 4 + i) * 32 + pw * 4 + j) * 32 + c4];
            sx += v.x; sy += v.y; sz += v.z; sw += v.w;
        }
    ((float4*)out)[idx] = make_float4(sx * 0.0625f, sy * 0.0625f, sz * 0.0625f, sw * 0.0625f);
}

// ======================= q GEMM (split-K, cp.async 4-stage, 1x8 thread map) =======================
#define GQ_SMEM_FLOATS (4 * 3328)
#define GQ_SMEM_BYTES (GQ_SMEM_FLOATS * 4)
__global__ __launch_bounds__(256, 3) void gemm_splitk_q(const float* __restrict__ Wm) {
    extern __shared__ float sg[];
    int nt = blockIdx.x, ks = blockIdx.y;
    int t = threadIdx.x;
    int tx = t & 7, ty = t >> 3;      // 8 col-groups x 32 rows
    float acc[8] = {};
    int n0 = nt * 64, kbase = ks * KSLEN;
    const float* A = g_qa;
    int ar = t >> 3, ac = (t & 7) * 4;
    int wr = t >> 4, wc = (t & 15) * 4;
    u32 sbase = smem_u32(sg);

#pragma unroll
    for (int s = 0; s < 4; s++) {
        int k0 = kbase + s * 32;
        u32 abase = sbase + (u32)(s * 3328) * 4u;
        u32 bbase = sbase + (u32)(s * 3328 + 1152) * 4u;
        CPA16(abase + (u32)(ar * 36 + ac) * 4u, &A[ar * QKIN + k0 + ac]);
        CPA16(bbase + (u32)(wr * 68 + wc) * 4u, &Wm[(k0 + wr) * TKD + n0 + wc]);
        CPA16(bbase + (u32)((wr + 16) * 68 + wc) * 4u, &Wm[(k0 + wr + 16) * TKD + n0 + wc]);
        asm volatile("cp.async.commit_group;");
    }

#pragma unroll
    for (int kt = 0; kt < 4; kt++) {
        if (kt == 0)      asm volatile("cp.async.wait_group 3;");
        else if (kt == 1) asm volatile("cp.async.wait_group 2;");
        else if (kt == 2) asm volatile("cp.async.wait_group 1;");
        else              asm volatile("cp.async.wait_group 0;");
        __syncthreads();
        const float* As = sg + kt * 3328;
        const float* Bs = As + 1152;
#pragma unroll
        for (int k = 0; k < 32; k++) {
            float a = As[ty * 36 + k];
            float4 b0 = *(const float4*)&Bs[k * 68 + tx * 8];
            float4 b1 = *(const float4*)&Bs[k * 68 + tx * 8 + 4];
            acc[0] = fmaf(a, b0.x, acc[0]); acc[1] = fmaf(a, b0.y, acc[1]);
            acc[2] = fmaf(a, b0.z, acc[2]); acc[3] = fmaf(a, b0.w, acc[3]);
            acc[4] = fmaf(a, b1.x, acc[4]); acc[5] = fmaf(a, b1.y, acc[5]);
            acc[6] = fmaf(a, b1.z, acc[6]); acc[7] = fmaf(a, b1.w, acc[7]);
        }
    }
    float* dst = &g_qpart[(ks * NB + ty) * TKD + n0 + tx * 8];
    *(float4*)&dst[0] = make_float4(acc[0], acc[1], acc[2], acc[3]);
    *(float4*)&dst[4] = make_float4(acc[4], acc[5], acc[6], acc[7]);
}

__global__ void reduce_q() {
    int idx = blockIdx.x * 256 + threadIdx.x;
    if (idx >= NB * TKD) return;
    float s = 0.f;
#pragma unroll
    for (int z = 0; z < KSLICES; z++) s += g_qpart[z * NB * TKD + idx];
    g_q[idx] = s;
}

// ======================= p vectors =======================
__global__ __launch_bounds__(256) void p_kernel(const float* __restrict__ wk) {
    int h = blockIdx.x;
    int j0 = blockIdx.y * 256;
    __shared__ float qs[32 * 64];
    __shared__ float ws[256 * 68];
    int t = threadIdx.x;
    for (int idx = t; idx < 512; idx += 256) {
        int b = idx >> 4, d4 = (idx & 15) * 4;
        *(float4*)&qs[b * 64 + d4] = *(const float4*)&g_q[b * TKD + h * DKH + d4];
    }
    for (int idx = t; idx < 256 * 16; idx += 256) {
        int row = idx >> 4, c4 = (idx & 15) * 4;
        *(float4*)&ws[row * 68 + c4] = *(const float4*)&wk[(j0 + row) * TKD + h * DKH + c4];
    }
    __syncthreads();
    float4 wr[16];
#pragma unroll
    for (int d4 = 0; d4 < 16; d4++) wr[d4] = *(const float4*)&ws[t * 68 + d4 * 4];
    int j = j0 + t;
    for (int b = 0; b < 32; b++) {
        float a = 0.f;
#pragma unroll
        for (int d4 = 0; d4 < 16; d4++) {
            float4 q4 = *(const float4*)&qs[b * 64 + d4 * 4];
            a = fmaf(wr[d4].x, q4.x, a);
            a = fmaf(wr[d4].y, q4.y, a);
            a = fmaf(wr[d4].z, q4.z, a);
            a = fmaf(wr[d4].w, q4.w, a);
        }
        g_p[(b * NHD + h) * QKIN + j] = a;
    }
}

// ======================= logits + rel-emb + softmax =======================
// grid (b,h). Warp w owns j-chunk w (1024 elems); ka and p each read ONCE per CTA.
__global__ __launch_bounds__(256) void logits_kernel(const float* __restrict__ tk) {
    __shared__ float red[8][8];
    __shared__ float rel[8];
    int b = blockIdx.x, h = blockIdx.y;
    int t = threadIdx.x;
    int w = t >> 5, lane = t & 31;
    const float* pp = g_p + (b * NHD + h) * QKIN + w * 1024;
    const float* ka = g_ka + b * NS * QKIN + w * 1024;
    float acc[8] = {};
#pragma unroll
    for (int jj = 0; jj < 8; jj++) {
        int j = lane * 4 + jj * 128;
        float4 pv = *(const float4*)&pp[j];
#pragma unroll
        for (int s = 0; s < 8; s++) {
            float4 kv = *(const float4*)&ka[s * QKIN + j];
            acc[s] = fmaf(kv.x, pv.x, acc[s]);
            acc[s] = fmaf(kv.y, pv.y, acc[s]);
            acc[s] = fmaf(kv.z, pv.z, acc[s]);
            acc[s] = fmaf(kv.w, pv.w, acc[s]);
        }
    }
#pragma unroll
    for (int s = 0; s < 8; s++)
#pragma unroll
        for (int off = 16; off; off >>= 1) acc[s] += __shfl_xor_sync(0xffffffffu, acc[s], off);
    if (lane == 0) {
#pragma unroll
        for (int s = 0; s < 8; s++) red[s][w] = acc[s];
    }
    if (w == 0) {    // rel-emb: q . z_k per s
        float q0 = g_q[b * TKD + h * DKH + lane];
        float q1 = g_q[b * TKD + h * DKH + 32 + lane];
#pragma unroll
        for (int s = 0; s < 8; s++) {
            int r = c_ridx[s];
            float v = q0 * tk[r * DKH + lane] + q1 * tk[r * DKH + 32 + lane];
#pragma unroll
            for (int off = 16; off; off >>= 1) v += __shfl_xor_sync(0xffffffffu, v, off);
            if (lane == 0) rel[s] = v;
        }
    }
    __syncthreads();
    if (t == 0) {
        float lg[8], m = -1e30f;
#pragma unroll
        for (int s = 0; s < 8; s++) {
            float d = rel[s];
#pragma unroll
            for (int ww = 0; ww < 8; ww++) d += red[s][ww];
            lg[s] = d * 0.125f;
            m = fmaxf(m, lg[s]);
        }
        float sum = 0.f;
#pragma unroll
        for (int s = 0; s < 8; s++) { lg[s] = expf(lg[s] - m); sum += lg[s]; }
        float inv = 1.f / sum;
#pragma unroll
        for (int s = 0; s < 8; s++) g_wgt[b * 64 + h * 8 + s] = lg[s] * inv;
    }
}

// ======================= vsum =======================
__global__ __launch_bounds__(256) void vsum_kernel(const float* __restrict__ v_ant) {
    int row = blockIdx.x, b = blockIdx.y;
    int ho = row >> 2;
    int hn = -1, side = 0;
    if ((row & 3) == 3 && ho < 7) { hn = ho + 1; side = 0; }
    else if ((row & 3) == 0 && ho > 0) { hn = ho - 1; side = 1; }
    __shared__ float swo[8];
    __shared__ float swn[8];
    int t = threadIdx.x;
    if (t < 8) swo[t] = g_wgt[b * 64 + ho * 8 + t];
    if (t >= 8 && t < 16 && hn >= 0) swn[t - 8] = g_wgt[b * 64 + hn * 8 + (t - 8)];
    __syncthreads();
    const float4* vp = (const float4*)v_ant;
    uint2* op = (uint2*)g_vsh;
    uint2* hp = (uint2*)g_vhh;
#pragma unroll
    for (int e = t; e < 1024; e += 256) {
        int gc = e >> 5, c4 = e & 31;
        int base = (b * 8 * 1024 + row * 32 + gc) * 32 + c4;
        float ax = 0.f, ay = 0.f, az = 0.f, aw = 0.f;
        float nx = 0.f, ny = 0.f, nz = 0.f, nw2 = 0.f;
#pragma unroll
        for (int s = 0; s < 8; s++) {
            float4 vv = vp[base + s * 32768];
            float w = swo[s];
            ax = fmaf(w, vv.x, ax); ay = fmaf(w, vv.y, ay);
            az = fmaf(w, vv.z, az); aw = fmaf(w, vv.w, aw);
            if (hn >= 0) {
                float w2 = swn[s];
                nx = fmaf(w2, vv.x, nx); ny = fmaf(w2, vv.y, ny);
                nz = fmaf(w2, vv.z, nz); nw2 = fmaf(w2, vv.w, nw2);
            }
        }
        op[(b * 1024 + row * 32 + gc) * 32 + c4] = make_uint2(h2(ax, ay), h2(az, aw));
        if (hn >= 0)
            hp[(((b * 8 + hn) * 2 + side) * 32 + gc) * 32 + c4] =
                make_uint2(h2(nx, ny), h2(nz, nw2));
    }
}

// ======================= weight fragment packer (fp16 frags) =======================
__global__ void wtrans_kernel(const float* __restrict__ cvw, const float* __restrict__ cow) {
    int t = blockIdx.x * 256 + threadIdx.x;
    if (t < 9 * 16 * 8 * 32) {
        int lane = t & 31, ks = (t >> 5) & 7, nt = (t >> 8) & 15, tap = t >> 12;
        int o = nt * 8 + (lane >> 2);
        int cin0 = ks * 16 + (lane & 3) * 2;
        float w00 = cvw[(tap * 128 + cin0) * 128 + o];
        float w01 = cvw[(tap * 128 + cin0 + 1) * 128 + o];
        float w10 = cvw[(tap * 128 + cin0 + 8) * 128 + o];
        float w11 = cvw[(tap * 128 + cin0 + 9) * 128 + o];
        g_wBv[t] = make_uint2(h2(w00, w01), h2(w10, w11));
    } else {
        int e = t - 9 * 16 * 8 * 32;
        if (e < 9 * 8 * 8 * 32) {
            int lane = e & 31, ks = (e >> 5) & 7, nt = (e >> 8) & 7, tap = e >> 11;
            int o = nt * 8 + (lane >> 2);
            int cin0 = ks * 16 + (lane & 3) * 2;
            float w00 = cow[(tap * 128 + cin0) * 64 + o];
            float w01 = cow[(tap * 128 + cin0 + 1) * 64 + o];
            float w10 = cow[(tap * 128 + cin0 + 8) * 64 + o];
            float w11 = cow[(tap * 128 + cin0 + 9) * 64 + o];
            g_wBo[e] = make_uint2(h2(w00, w01), h2(w10, w11));
        }
    }
}

// smem: s_w 4096 uint2 (32768 B) | s_wgt 8 floats (32 B) | s_in 204*136 half (55488 B)
#define CV_SMEM_BYTES (32768 + 32 + 204 * 136 * 2)

// ======================= conv_v (fp16 mma) =======================
__global__ __launch_bounds__(256, 2) void conv_v_kernel(
    const float* __restrict__ cvb, const float* __restrict__ tv) {
    int h = blockIdx.x, b = blockIdx.y;
    extern __shared__ char smraw[];
    uint2* s_w = (uint2*)smraw;
    float* s_wgt = (float*)(smraw + 32768);
    __half* s_in = (__half*)(smraw + 32800);
    int t = threadIdx.x;
    int wid = t >> 5, lane = t & 31;
    if (t < 8) s_wgt[t] = g_wgt[b * 64 + h * 8 + t];

    const uint2* vs = (const uint2*)g_vsh;
    const uint2* vh = (const uint2*)g_vhh;
    for (int e = t; e < 6 * 34 * 32; e += 256) {
        int c4 = e & 31;
        int ci = (e >> 5) % 34;
        int ri = e / (34 * 32);
        int gr = h * 4 - 1 + ri;
        int gc = ci - 1;
        uint2 v = make_uint2(0u, 0u);
        if (gr >= 0 && gr < 32 && gc >= 0 && gc < 32) {
            if (ri == 0)
                v = vh[(((b * 8 + h) * 2 + 0) * 32 + gc) * 32 + c4];
            else if (ri == 5)
                v = vh[(((b * 8 + h) * 2 + 1) * 32 + gc) * 32 + c4];
            else
                v = vs[(b * 1024 + gr * 32 + gc) * 32 + c4];
        }
        *(uint2*)&s_in[(ri * 34 + ci) * 136 + c4 * 4] = v;
    }

    int mw = wid >> 1, nw = wid & 1;
    float4 acc[2][8];
#pragma unroll
    for (int m = 0; m < 2; m++)
#pragma unroll
        for (int nt = 0; nt < 8; nt++) acc[m][nt] = make_float4(0.f, 0.f, 0.f, 0.f);

    for (int tap = 0; tap < 9; tap++) {
        __syncthreads();
        const uint2* srcw = g_wBv + tap * 4096;
        for (int e = t; e < 4096; e += 256) s_w[e] = srcw[e];
        __syncthreads();
        int dy = tap / 3 - 1, dx = tap % 3 - 1;
        const __half* ab = s_in + ((mw + 1 + dy) * 34 + 1 + dx) * 136;
#pragma unroll
        for (int k = 0; k < 8; k++) {
            int cin0 = k * 16 + (lane & 3) * 2;
            u32 a[2][4];
#pragma unroll
            for (int m = 0; m < 2; m++) {
                int c = m * 16 + (lane >> 2);
                a[m][0] = *(const u32*)&ab[c * 136 + cin0];
                a[m][1] = *(const u32*)&ab[(c + 8) * 136 + cin0];
                a[m][2] = *(const u32*)&ab[c * 136 + cin0 + 8];
                a[m][3] = *(const u32*)&ab[(c + 8) * 136 + cin0 + 8];
            }
#pragma unroll
            for (int nt = 0; nt < 8; nt++) {
                uint2 bv = s_w[((nw * 8 + nt) * 8 + k) * 32 + lane];
                mma_f16(acc[0][nt], a[0], bv);
                mma_f16(acc[1][nt], a[1], bv);
            }
        }
    }

    float W0 = s_wgt[0] + s_wgt[1] + s_wgt[2] + s_wgt[3] + s_wgt[4];
    float w5 = s_wgt[5], w6 = s_wgt[6], w7 = s_wgt[7];
    const float2* tv2 = (const float2*)tv;
#pragma unroll
    for (int m = 0; m < 2; m++) {
#pragma unroll
        for (int half = 0; half < 2; half++) {
            int p = mw * 32 + m * 16 + (lane >> 2) + half * 8;
            int gr = h * 4 + (p >> 5), gc = p & 31;
            __half* dst = &g_xh[(b * 1024 + gr * 32 + gc) * 128];
#pragma unroll
            for (int nt = 0; nt < 8; nt++) {
                int o = nw * 64 + nt * 8 + (lane & 3) * 2;
                int ti = p * 64 + (o >> 1);
                float2 z0 = tv2[ti];
                float2 z1 = tv2[8192 + ti];
                float2 z2 = tv2[16384 + ti];
                float2 z3 = tv2[24576 + ti];
                float2 bias = *(const float2*)&cvb[o];
                float ax = half ? acc[m][nt].z : acc[m][nt].x;
                float ay = half ? acc[m][nt].w : acc[m][nt].y;
                float rx = ax + bias.x + W0 * z0.x + w5 * z1.x + w6 * z2.x + w7 * z3.x;
                float ry = ay + bias.y + W0 * z0.y + w5 * z1.y + w6 * z2.y + w7 * z3.y;
                *(u32*)&dst[o] = h2(rx, ry);
            }
        }
    }
}

// smem: s_w 2048 uint2 (16384 B) | s_in 204*136 half (55488 B)
#define CO_SMEM_BYTES (16384 + 204 * 136 * 2)

// ======================= conv_o (fp16 mma) =======================
__global__ __launch_bounds__(256, 2) void conv_o_kernel(
    const float* __restrict__ cob, float* __restrict__ out) {
    int rb = blockIdx.x, b = blockIdx.y;
    extern __shared__ char smraw[];
    uint2* s_w = (uint2*)smraw;
    __half* s_in = (__half*)(smraw + 16384);
    int t = threadIdx.x;
    int wid = t >> 5, lane = t & 31;

    const uint2* xs = (const uint2*)g_xh;
    for (int e = t; e < 6 * 34 * 32; e += 256) {
        int c4 = e & 31;
        int ci = (e >> 5) % 34;
        int ri = e / (34 * 32);
        int gr = rb * 4 - 1 + ri, gc = ci - 1;
        uint2 v = make_uint2(0u, 0u);
        if (gr >= 0 && gr < 32 && gc >= 0 && gc < 32)
            v = xs[(b * 1024 + gr * 32 + gc) * 32 + c4];
        *(uint2*)&s_in[(ri * 34 + ci) * 136 + c4 * 4] = v;
    }

    int mw = wid >> 1, nw = wid & 1;
    float4 acc[2][4];
#pragma unroll
    for (int m = 0; m < 2; m++)
#pragma unroll
        for (int nt = 0; nt < 4; nt++) acc[m][nt] = make_float4(0.f, 0.f, 0.f, 0.f);

    for (int tap = 0; tap < 9; tap++) {
        __syncthreads();
        const uint2* srcw = g_wBo + tap * 2048;
        for (int e = t; e < 2048; e += 256) s_w[e] = srcw[e];
        __syncthreads();
        int dy = tap / 3 - 1, dx = tap % 3 - 1;
        const __half* ab = s_in + ((mw + 1 + dy) * 34 + 1 + dx) * 136;
#pragma unroll
        for (int k = 0; k < 8; k++) {
            int cin0 = k * 16 + (lane & 3) * 2;
            u32 a[2][4];
#pragma unroll
            for (int m = 0; m < 2; m++) {
                int c = m * 16 + (lane >> 2);
                a[m][0] = *(const u32*)&ab[c * 136 + cin0];
                a[m][1] = *(const u32*)&ab[(c + 8) * 136 + cin0];
                a[m][2] = *(const u32*)&ab[c * 136 + cin0 + 8];
                a[m][3] = *(const u32*)&ab[(c + 8) * 136 + cin0 + 8];
            }
#pragma unroll
            for (int nt = 0; nt < 4; nt++) {
                uint2 bv = s_w[((nw * 4 + nt) * 8 + k) * 32 + lane];
                mma_f16(acc[0][nt], a[0], bv);
                mma_f16(acc[1][nt], a[1], bv);
            }
        }
    }

#pragma unroll
    for (int m = 0; m < 2; m++) {
#pragma unroll
        for (int half = 0; half < 2; half++) {
            int p = mw * 32 + m * 16 + (lane >> 2) + half * 8;
            int gr = rb * 4 + (p >> 5), gc = p & 31;
            float* dst = &out[(b * 1024 + gr * 32 + gc) * 64];
#pragma unroll
            for (int nt = 0; nt < 4; nt++) {
                int o = nw * 32 + nt * 8 + (lane & 3) * 2;
                float2 bias = *(const float2*)&cob[o];
                float ax = half ? acc[m][nt].z : acc[m][nt].x;
                float ay = half ? acc[m][nt].w : acc[m][nt].y;
                float2 r;
                r.x = ax + bias.x;
                r.y = ay + bias.y;
                *(float2*)&dst[o] = r;
            }
        }
    }
}

extern "C" void kernel_launch(void* const* d_in, const int* in_sizes, int n_in,
                              void* d_out, int out_size) {
    const float* inputs = (const float*)d_in[0];
    const float* k_ant  = (const float*)d_in[1];
    const float* v_ant  = (const float*)d_in[2];
    const float* w_q    = (const float*)d_in[3];
    const float* w_k    = (const float*)d_in[4];
    const float* cvw    = (const float*)d_in[5];
    const float* cvb    = (const float*)d_in[6];
    const float* cow    = (const float*)d_in[7];
    const float* cob    = (const float*)d_in[8];
    const float* tk     = (const float*)d_in[9];
    const float* tv     = (const float*)d_in[10];
    float* out = (float*)d_out;

    static bool s_init = false;
    static cudaStream_t s1, s2;
    static cudaEvent_t ev0, ev1, ev2;
    if (!s_init) {
        cudaStreamCreateWithFlags(&s1, cudaStreamNonBlocking);
        cudaStreamCreateWithFlags(&s2, cudaStreamNonBlocking);
        cudaEventCreateWithFlags(&ev0, cudaEventDisableTiming);
        cudaEventCreateWithFlags(&ev1, cudaEventDisableTiming);
        cudaEventCreateWithFlags(&ev2, cudaEventDisableTiming);
        cudaFuncSetAttribute(conv_v_kernel, cudaFuncAttributeMaxDynamicSharedMemorySize, CV_SMEM_BYTES);
        cudaFuncSetAttribute(conv_o_kernel, cudaFuncAttributeMaxDynamicSharedMemorySize, CO_SMEM_BYTES);
        cudaFuncSetAttribute(gemm_splitk_q, cudaFuncAttributeMaxDynamicSharedMemorySize, GQ_SMEM_BYTES);
        s_init = true;
    }

    cudaStream_t origin = (cudaStream_t)0;
    cudaStreamCaptureStatus cs = cudaStreamCaptureStatusNone;
    cudaStreamIsCapturing(cudaStreamPerThread, &cs);
    if (cs == cudaStreamCaptureStatusActive) {
        origin = cudaStreamPerThread;
    } else {
        cudaStreamIsCapturing(cudaStreamLegacy, &cs);
        if (cs == cudaStreamCaptureStatusActive) origin = cudaStreamLegacy;
    }

    // fork side branches
    cudaEventRecord(ev0, origin);
    cudaStreamWaitEvent(s1, ev0, 0);
    cudaStreamWaitEvent(s2, ev0, 0);

    // branch 1: pool of k_antecedent
    pool_kernel<<<(NB * NS * 2048 + 255) / 256, 256, 0, s1>>>(k_ant, NB * NS, 1);
    cudaEventRecord(ev1, s1);

    // branch 2: conv weight fp16 fragment packing
    wtrans_kernel<<<(9 * 16 * 8 * 32 + 9 * 8 * 8 * 32 + 255) / 256, 256, 0, s2>>>(cvw, cow);
    cudaEventRecord(ev2, s2);

    // main chain: q path
    pool_kernel<<<(NB * 2048 + 255) / 256, 256, 0, origin>>>(inputs, NB, 0);
    gemm_splitk_q<<<dim3(8, KSLICES), 256, GQ_SMEM_BYTES, origin>>>(w_q);
    reduce_q<<<(NB * TKD + 255) / 256, 256, 0, origin>>>();
    p_kernel<<<dim3(NHD, 32), 256, 0, origin>>>(w_k);

    // join pool_k, then logits+softmax (ka and p each read once per CTA)
    cudaStreamWaitEvent(origin, ev1, 0);
    logits_kernel<<<dim3(NB, NHD), 256, 0, origin>>>(tk);

    // weighted V sum -> half
    vsum_kernel<<<dim3(32, NB), 256, 0, origin>>>(v_ant);

    // join wtrans, then convs (full-batch launches, 2 CTA/SM)
    cudaStreamWaitEvent(origin, ev2, 0);
    conv_v_kernel<<<dim3(NHD, NB), 256, CV_SMEM_BYTES, origin>>>(cvb, tv);
    conv_o_kernel<<<dim3(8, NB), 256, CO_SMEM_BYTES, origin>>>(cob, out);
}

// round 17
// speedup vs baseline: 1.5391x; 1.5391x over previous
#include <cuda_runtime.h>
#include <cuda_fp16.h>
#include <cstdint>

#define NB 32
#define NS 8
#define NHD 8
#define QKIN 8192
#define TKD 512
#define DKH 64
#define KSLICES 64
#define KSLEN 128

typedef unsigned long long u64;
typedef unsigned int u32;

// ---- scratch (static __device__ globals; no allocations) ----
__device__ float g_qa[NB * QKIN];
__device__ float g_ka[NB * NS * QKIN];
__device__ float g_qpart[KSLICES * NB * TKD];
__device__ float g_q[NB * TKD];
__device__ float g_p[NB * NHD * QKIN];
__device__ float g_wgt[NB * NHD * NS];
__device__ __half g_vsh[NB * 1024 * 128];            // weighted V (own head), half
__device__ __half g_vhh[NB * NHD * 2 * 32 * 128];    // halo rows (consumer-head weighted)
__device__ __half g_xh[NB * 1024 * 128];             // conv_v output, half
__device__ uint2 g_wBv[9 * 16 * 8 * 32];             // fp16 B frags conv_v
__device__ uint2 g_wBo[9 * 8 * 8 * 32];              // fp16 B frags conv_o

__constant__ int c_ridx[8] = {0, 0, 0, 0, 0, 1, 2, 3};

__device__ __forceinline__ u32 h2(float a, float b) {
    __half2 v = __float22half2_rn(make_float2(a, b));
    return *(u32*)&v;
}

__device__ __forceinline__ u32 smem_u32(const void* p) {
    u32 a;
    asm("{ .reg .u64 t; cvta.to.shared.u64 t, %1; cvt.u32.u64 %0, t; }" : "=r"(a) : "l"(p));
    return a;
}

#define CPA16(dst, src) \
    asm volatile("cp.async.ca.shared.global [%0], [%1], 16;" :: "r"(dst), "l"(src))

__device__ __forceinline__ void mma_f16(float4& d, const u32* a, uint2 b) {
    asm volatile("mma.sync.aligned.m16n8k16.row.col.f32.f16.f16.f32 "
        "{%0,%1,%2,%3}, {%4,%5,%6,%7}, {%8,%9}, {%0,%1,%2,%3};"
        : "+f"(d.x), "+f"(d.y), "+f"(d.z), "+f"(d.w)
        : "r"(a[0]), "r"(a[1]), "r"(a[2]), "r"(a[3]), "r"(b.x), "r"(b.y));
}

// ======================= pool =======================
__global__ void pool_kernel(const float* __restrict__ in, int nImg, int which) {
    float* out = which ? g_ka : g_qa;
    int idx = blockIdx.x * 256 + threadIdx.x;
    if (idx >= nImg * 2048) return;
    int c4 = idx & 31;
    int pw = (idx >> 5) & 7;
    int ph = (idx >> 8) & 7;
    int img = idx >> 11;
    const float4* p4 = (const float4*)in;
    float sx = 0.f, sy = 0.f, sz = 0.f, sw = 0.f;
#pragma unroll
    for (int i = 0; i < 4; i++)
#pragma unroll
        for (int j = 0; j < 4; j++) {
            float4 v = p4[((img * 32 + ph * 4 + i) * 32 + pw * 4 + j) * 32 + c4];
            sx += v.x; sy += v.y; sz += v.z; sw += v.w;
        }
    ((float4*)out)[idx] = make_float4(sx * 0.0625f, sy * 0.0625f, sz * 0.0625f, sw * 0.0625f);
}

// ======================= q GEMM (split-K, cp.async 4-stage, 2x4 thread map) =======================
#define GQ_SMEM_FLOATS (4 * 3328)
#define GQ_SMEM_BYTES (GQ_SMEM_FLOATS * 4)
__global__ __launch_bounds__(256, 3) void gemm_splitk_q(const float* __restrict__ Wm) {
    extern __shared__ float sg[];
    int nt = blockIdx.x, ks = blockIdx.y;
    int t = threadIdx.x;
    int tx = t & 15, ty = t >> 4;
    float acc[2][4] = {};
    int n0 = nt * 64, kbase = ks * KSLEN;
    const float* A = g_qa;
    int ar = t >> 3, ac = (t & 7) * 4;
    int wr = t >> 4, wc = (t & 15) * 4;
    u32 sbase = smem_u32(sg);

#pragma unroll
    for (int s = 0; s < 4; s++) {
        int k0 = kbase + s * 32;
        u32 abase = sbase + (u32)(s * 3328) * 4u;
        u32 bbase = sbase + (u32)(s * 3328 + 1152) * 4u;
        CPA16(abase + (u32)(ar * 36 + ac) * 4u, &A[ar * QKIN + k0 + ac]);
        CPA16(bbase + (u32)(wr * 68 + wc) * 4u, &Wm[(k0 + wr) * TKD + n0 + wc]);
        CPA16(bbase + (u32)((wr + 16) * 68 + wc) * 4u, &Wm[(k0 + wr + 16) * TKD + n0 + wc]);
        asm volatile("cp.async.commit_group;");
    }

#pragma unroll
    for (int kt = 0; kt < 4; kt++) {
        if (kt == 0)      asm volatile("cp.async.wait_group 3;");
        else if (kt == 1) asm volatile("cp.async.wait_group 2;");
        else if (kt == 2) asm volatile("cp.async.wait_group 1;");
        else              asm volatile("cp.async.wait_group 0;");
        __syncthreads();
        const float* As = sg + kt * 3328;
        const float* Bs = As + 1152;
#pragma unroll
        for (int k = 0; k < 32; k++) {
            float a0 = As[(ty * 2) * 36 + k], a1 = As[(ty * 2 + 1) * 36 + k];
            float4 bv = *(const float4*)&Bs[k * 68 + tx * 4];
            acc[0][0] = fmaf(a0, bv.x, acc[0][0]); acc[0][1] = fmaf(a0, bv.y, acc[0][1]);
            acc[0][2] = fmaf(a0, bv.z, acc[0][2]); acc[0][3] = fmaf(a0, bv.w, acc[0][3]);
            acc[1][0] = fmaf(a1, bv.x, acc[1][0]); acc[1][1] = fmaf(a1, bv.y, acc[1][1]);
            acc[1][2] = fmaf(a1, bv.z, acc[1][2]); acc[1][3] = fmaf(a1, bv.w, acc[1][3]);
        }
    }
#pragma unroll
    for (int r = 0; r < 2; r++)
#pragma unroll
        for (int c = 0; c < 4; c++)
            g_qpart[(ks * NB + ty * 2 + r) * TKD + n0 + tx * 4 + c] = acc[r][c];
}

__global__ void reduce_q() {
    int idx = blockIdx.x * 256 + threadIdx.x;
    if (idx >= NB * TKD) return;
    float s = 0.f;
#pragma unroll
    for (int z = 0; z < KSLICES; z++) s += g_qpart[z * NB * TKD + idx];
    g_q[idx] = s;
}

// ======================= p vectors =======================
__global__ __launch_bounds__(256) void p_kernel(const float* __restrict__ wk) {
    int h = blockIdx.x;
    int j0 = blockIdx.y * 256;
    __shared__ float qs[32 * 64];
    __shared__ float ws[256 * 68];
    int t = threadIdx.x;
    for (int idx = t; idx < 512; idx += 256) {
        int b = idx >> 4, d4 = (idx & 15) * 4;
        *(float4*)&qs[b * 64 + d4] = *(const float4*)&g_q[b * TKD + h * DKH + d4];
    }
    for (int idx = t; idx < 256 * 16; idx += 256) {
        int row = idx >> 4, c4 = (idx & 15) * 4;
        *(float4*)&ws[row * 68 + c4] = *(const float4*)&wk[(j0 + row) * TKD + h * DKH + c4];
    }
    __syncthreads();
    float4 wr[16];
#pragma unroll
    for (int d4 = 0; d4 < 16; d4++) wr[d4] = *(const float4*)&ws[t * 68 + d4 * 4];
    int j = j0 + t;
    for (int b = 0; b < 32; b++) {
        float a = 0.f;
#pragma unroll
        for (int d4 = 0; d4 < 16; d4++) {
            float4 q4 = *(const float4*)&qs[b * 64 + d4 * 4];
            a = fmaf(wr[d4].x, q4.x, a);
            a = fmaf(wr[d4].y, q4.y, a);
            a = fmaf(wr[d4].z, q4.z, a);
            a = fmaf(wr[d4].w, q4.w, a);
        }
        g_p[(b * NHD + h) * QKIN + j] = a;
    }
}

// ======================= logits + rel-emb + softmax =======================
// grid (b,h). Warp w owns j-chunk w (1024 elems); ka and p each read ONCE per CTA.
__global__ __launch_bounds__(256) void logits_kernel(const float* __restrict__ tk) {
    __shared__ float red[8][8];
    __shared__ float rel[8];
    int b = blockIdx.x, h = blockIdx.y;
    int t = threadIdx.x;
    int w = t >> 5, lane = t & 31;
    const float* pp = g_p + (b * NHD + h) * QKIN + w * 1024;
    const float* ka = g_ka + b * NS * QKIN + w * 1024;
    float acc[8] = {};
#pragma unroll
    for (int jj = 0; jj < 8; jj++) {
        int j = lane * 4 + jj * 128;
        float4 pv = *(const float4*)&pp[j];
#pragma unroll
        for (int s = 0; s < 8; s++) {
            float4 kv = *(const float4*)&ka[s * QKIN + j];
            acc[s] = fmaf(kv.x, pv.x, acc[s]);
            acc[s] = fmaf(kv.y, pv.y, acc[s]);
            acc[s] = fmaf(kv.z, pv.z, acc[s]);
            acc[s] = fmaf(kv.w, pv.w, acc[s]);
        }
    }
#pragma unroll
    for (int s = 0; s < 8; s++)
#pragma unroll
        for (int off = 16; off; off >>= 1) acc[s] += __shfl_xor_sync(0xffffffffu, acc[s], off);
    if (lane == 0) {
#pragma unroll
        for (int s = 0; s < 8; s++) red[s][w] = acc[s];
    }
    if (w == 0) {    // rel-emb: q . z_k per s
        float q0 = g_q[b * TKD + h * DKH + lane];
        float q1 = g_q[b * TKD + h * DKH + 32 + lane];
#pragma unroll
        for (int s = 0; s < 8; s++) {
            int r = c_ridx[s];
            float v = q0 * tk[r * DKH + lane] + q1 * tk[r * DKH + 32 + lane];
#pragma unroll
            for (int off = 16; off; off >>= 1) v += __shfl_xor_sync(0xffffffffu, v, off);
            if (lane == 0) rel[s] = v;
        }
    }
    __syncthreads();
    if (t == 0) {
        float lg[8], m = -1e30f;
#pragma unroll
        for (int s = 0; s < 8; s++) {
            float d = rel[s];
#pragma unroll
            for (int ww = 0; ww < 8; ww++) d += red[s][ww];
            lg[s] = d * 0.125f;
            m = fmaxf(m, lg[s]);
        }
        float sum = 0.f;
#pragma unroll
        for (int s = 0; s < 8; s++) { lg[s] = expf(lg[s] - m); sum += lg[s]; }
        float inv = 1.f / sum;
#pragma unroll
        for (int s = 0; s < 8; s++) g_wgt[b * 64 + h * 8 + s] = lg[s] * inv;
    }
}

// ======================= vsum =======================
__global__ __launch_bounds__(256) void vsum_kernel(const float* __restrict__ v_ant) {
    int row = blockIdx.x, b = blockIdx.y;
    int ho = row >> 2;
    int hn = -1, side = 0;
    if ((row & 3) == 3 && ho < 7) { hn = ho + 1; side = 0; }
    else if ((row & 3) == 0 && ho > 0) { hn = ho - 1; side = 1; }
    __shared__ float swo[8];
    __shared__ float swn[8];
    int t = threadIdx.x;
    if (t < 8) swo[t] = g_wgt[b * 64 + ho * 8 + t];
    if (t >= 8 && t < 16 && hn >= 0) swn[t - 8] = g_wgt[b * 64 + hn * 8 + (t - 8)];
    __syncthreads();
    const float4* vp = (const float4*)v_ant;
    uint2* op = (uint2*)g_vsh;
    uint2* hp = (uint2*)g_vhh;
#pragma unroll
    for (int e = t; e < 1024; e += 256) {
        int gc = e >> 5, c4 = e & 31;
        int base = (b * 8 * 1024 + row * 32 + gc) * 32 + c4;
        float ax = 0.f, ay = 0.f, az = 0.f, aw = 0.f;
        float nx = 0.f, ny = 0.f, nz = 0.f, nw2 = 0.f;
#pragma unroll
        for (int s = 0; s < 8; s++) {
            float4 vv = vp[base + s * 32768];
            float w = swo[s];
            ax = fmaf(w, vv.x, ax); ay = fmaf(w, vv.y, ay);
            az = fmaf(w, vv.z, az); aw = fmaf(w, vv.w, aw);
            if (hn >= 0) {
                float w2 = swn[s];
                nx = fmaf(w2, vv.x, nx); ny = fmaf(w2, vv.y, ny);
                nz = fmaf(w2, vv.z, nz); nw2 = fmaf(w2, vv.w, nw2);
            }
        }
        op[(b * 1024 + row * 32 + gc) * 32 + c4] = make_uint2(h2(ax, ay), h2(az, aw));
        if (hn >= 0)
            hp[(((b * 8 + hn) * 2 + side) * 32 + gc) * 32 + c4] =
                make_uint2(h2(nx, ny), h2(nz, nw2));
    }
}

// ======================= weight fragment packer (fp16 frags) =======================
__global__ void wtrans_kernel(const float* __restrict__ cvw, const float* __restrict__ cow) {
    int t = blockIdx.x * 256 + threadIdx.x;
    if (t < 9 * 16 * 8 * 32) {
        int lane = t & 31, ks = (t >> 5) & 7, nt = (t >> 8) & 15, tap = t >> 12;
        int o = nt * 8 + (lane >> 2);
        int cin0 = ks * 16 + (lane & 3) * 2;
        float w00 = cvw[(tap * 128 + cin0) * 128 + o];
        float w01 = cvw[(tap * 128 + cin0 + 1) * 128 + o];
        float w10 = cvw[(tap * 128 + cin0 + 8) * 128 + o];
        float w11 = cvw[(tap * 128 + cin0 + 9) * 128 + o];
        g_wBv[t] = make_uint2(h2(w00, w01), h2(w10, w11));
    } else {
        int e = t - 9 * 16 * 8 * 32;
        if (e < 9 * 8 * 8 * 32) {
            int lane = e & 31, ks = (e >> 5) & 7, nt = (e >> 8) & 7, tap = e >> 11;
            int o = nt * 8 + (lane >> 2);
            int cin0 = ks * 16 + (lane & 3) * 2;
            float w00 = cow[(tap * 128 + cin0) * 64 + o];
            float w01 = cow[(tap * 128 + cin0 + 1) * 64 + o];
            float w10 = cow[(tap * 128 + cin0 + 8) * 64 + o];
            float w11 = cow[(tap * 128 + cin0 + 9) * 64 + o];
            g_wBo[e] = make_uint2(h2(w00, w01), h2(w10, w11));
        }
    }
}

// smem: s_w 4096 uint2 (32768 B) | s_wgt 8 floats (32 B) | s_in 204*136 half (55488 B)
#define CV_SMEM_BYTES (32768 + 32 + 204 * 136 * 2)

// ======================= conv_v (fp16 mma) =======================
__global__ __launch_bounds__(256, 2) void conv_v_kernel(
    const float* __restrict__ cvb, const float* __restrict__ tv) {
    int h = blockIdx.x, b = blockIdx.y;
    extern __shared__ char smraw[];
    uint2* s_w = (uint2*)smraw;
    float* s_wgt = (float*)(smraw + 32768);
    __half* s_in = (__half*)(smraw + 32800);
    int t = threadIdx.x;
    int wid = t >> 5, lane = t & 31;
    if (t < 8) s_wgt[t] = g_wgt[b * 64 + h * 8 + t];

    const uint2* vs = (const uint2*)g_vsh;
    const uint2* vh = (const uint2*)g_vhh;
    for (int e = t; e < 6 * 34 * 32; e += 256) {
        int c4 = e & 31;
        int ci = (e >> 5) % 34;
        int ri = e / (34 * 32);
        int gr = h * 4 - 1 + ri;
        int gc = ci - 1;
        uint2 v = make_uint2(0u, 0u);
        if (gr >= 0 && gr < 32 && gc >= 0 && gc < 32) {
            if (ri == 0)
                v = vh[(((b * 8 + h) * 2 + 0) * 32 + gc) * 32 + c4];
            else if (ri == 5)
                v = vh[(((b * 8 + h) * 2 + 1) * 32 + gc) * 32 + c4];
            else
                v = vs[(b * 1024 + gr * 32 + gc) * 32 + c4];
        }
        *(uint2*)&s_in[(ri * 34 + ci) * 136 + c4 * 4] = v;
    }

    int mw = wid >> 1, nw = wid & 1;
    float4 acc[2][8];
#pragma unroll
    for (int m = 0; m < 2; m++)
#pragma unroll
        for (int nt = 0; nt < 8; nt++) acc[m][nt] = make_float4(0.f, 0.f, 0.f, 0.f);

    for (int tap = 0; tap < 9; tap++) {
        __syncthreads();
        const uint2* srcw = g_wBv + tap * 4096;
        for (int e = t; e < 4096; e += 256) s_w[e] = srcw[e];
        __syncthreads();
        int dy = tap / 3 - 1, dx = tap % 3 - 1;
        const __half* ab = s_in + ((mw + 1 + dy) * 34 + 1 + dx) * 136;
#pragma unroll
        for (int k = 0; k < 8; k++) {
            int cin0 = k * 16 + (lane & 3) * 2;
            u32 a[2][4];
#pragma unroll
            for (int m = 0; m < 2; m++) {
                int c = m * 16 + (lane >> 2);
                a[m][0] = *(const u32*)&ab[c * 136 + cin0];
                a[m][1] = *(const u32*)&ab[(c + 8) * 136 + cin0];
                a[m][2] = *(const u32*)&ab[c * 136 + cin0 + 8];
                a[m][3] = *(const u32*)&ab[(c + 8) * 136 + cin0 + 8];
            }
#pragma unroll
            for (int nt = 0; nt < 8; nt++) {
                uint2 bv = s_w[((nw * 8 + nt) * 8 + k) * 32 + lane];
                mma_f16(acc[0][nt], a[0], bv);
                mma_f16(acc[1][nt], a[1], bv);
            }
        }
    }

    float W0 = s_wgt[0] + s_wgt[1] + s_wgt[2] + s_wgt[3] + s_wgt[4];
    float w5 = s_wgt[5], w6 = s_wgt[6], w7 = s_wgt[7];
    const float2* tv2 = (const float2*)tv;
#pragma unroll
    for (int m = 0; m < 2; m++) {
#pragma unroll
        for (int half = 0; half < 2; half++) {
            int p = mw * 32 + m * 16 + (lane >> 2) + half * 8;
            int gr = h * 4 + (p >> 5), gc = p & 31;
            __half* dst = &g_xh[(b * 1024 + gr * 32 + gc) * 128];
#pragma unroll
            for (int nt = 0; nt < 8; nt++) {
                int o = nw * 64 + nt * 8 + (lane & 3) * 2;
                int ti = p * 64 + (o >> 1);
                float2 z0 = tv2[ti];
                float2 z1 = tv2[8192 + ti];
                float2 z2 = tv2[16384 + ti];
                float2 z3 = tv2[24576 + ti];
                float2 bias = *(const float2*)&cvb[o];
                float ax = half ? acc[m][nt].z : acc[m][nt].x;
                float ay = half ? acc[m][nt].w : acc[m][nt].y;
                float rx = ax + bias.x + W0 * z0.x + w5 * z1.x + w6 * z2.x + w7 * z3.x;
                float ry = ay + bias.y + W0 * z0.y + w5 * z1.y + w6 * z2.y + w7 * z3.y;
                *(u32*)&dst[o] = h2(rx, ry);
            }
        }
    }
}

// smem: s_w 2048 uint2 (16384 B) | s_in 204*136 half (55488 B)
#define CO_SMEM_BYTES (16384 + 204 * 136 * 2)

// ======================= conv_o (fp16 mma) =======================
__global__ __launch_bounds__(256, 2) void conv_o_kernel(
    const float* __restrict__ cob, float* __restrict__ out) {
    int rb = blockIdx.x, b = blockIdx.y;
    extern __shared__ char smraw[];
    uint2* s_w = (uint2*)smraw;
    __half* s_in = (__half*)(smraw + 16384);
    int t = threadIdx.x;
    int wid = t >> 5, lane = t & 31;

    const uint2* xs = (const uint2*)g_xh;
    for (int e = t; e < 6 * 34 * 32; e += 256) {
        int c4 = e & 31;
        int ci = (e >> 5) % 34;
        int ri = e / (34 * 32);
        int gr = rb * 4 - 1 + ri, gc = ci - 1;
        uint2 v = make_uint2(0u, 0u);
        if (gr >= 0 && gr < 32 && gc >= 0 && gc < 32)
            v = xs[(b * 1024 + gr * 32 + gc) * 32 + c4];
        *(uint2*)&s_in[(ri * 34 + ci) * 136 + c4 * 4] = v;
    }

    int mw = wid >> 1, nw = wid & 1;
    float4 acc[2][4];
#pragma unroll
    for (int m = 0; m < 2; m++)
#pragma unroll
        for (int nt = 0; nt < 4; nt++) acc[m][nt] = make_float4(0.f, 0.f, 0.f, 0.f);

    for (int tap = 0; tap < 9; tap++) {
        __syncthreads();
        const uint2* srcw = g_wBo + tap * 2048;
        for (int e = t; e < 2048; e += 256) s_w[e] = srcw[e];
        __syncthreads();
        int dy = tap / 3 - 1, dx = tap % 3 - 1;
        const __half* ab = s_in + ((mw + 1 + dy) * 34 + 1 + dx) * 136;
#pragma unroll
        for (int k = 0; k < 8; k++) {
            int cin0 = k * 16 + (lane & 3) * 2;
            u32 a[2][4];
#pragma unroll
            for (int m = 0; m < 2; m++) {
                int c = m * 16 + (lane >> 2);
                a[m][0] = *(const u32*)&ab[c * 136 + cin0];
                a[m][1] = *(const u32*)&ab[(c + 8) * 136 + cin0];
                a[m][2] = *(const u32*)&ab[c * 136 + cin0 + 8];
                a[m][3] = *(const u32*)&ab[(c + 8) * 136 + cin0 + 8];
            }
#pragma unroll
            for (int nt = 0; nt < 4; nt++) {
                uint2 bv = s_w[((nw * 4 + nt) * 8 + k) * 32 + lane];
                mma_f16(acc[0][nt], a[0], bv);
                mma_f16(acc[1][nt], a[1], bv);
            }
        }
    }

#pragma unroll
    for (int m = 0; m < 2; m++) {
#pragma unroll
        for (int half = 0; half < 2; half++) {
            int p = mw * 32 + m * 16 + (lane >> 2) + half * 8;
            int gr = rb * 4 + (p >> 5), gc = p & 31;
            float* dst = &out[(b * 1024 + gr * 32 + gc) * 64];
#pragma unroll
            for (int nt = 0; nt < 4; nt++) {
                int o = nw * 32 + nt * 8 + (lane & 3) * 2;
                float2 bias = *(const float2*)&cob[o];
                float ax = half ? acc[m][nt].z : acc[m][nt].x;
                float ay = half ? acc[m][nt].w : acc[m][nt].y;
                float2 r;
                r.x = ax + bias.x;
                r.y = ay + bias.y;
                *(float2*)&dst[o] = r;
            }
        }
    }
}

extern "C" void kernel_launch(void* const* d_in, const int* in_sizes, int n_in,
                              void* d_out, int out_size) {
    const float* inputs = (const float*)d_in[0];
    const float* k_ant  = (const float*)d_in[1];
    const float* v_ant  = (const float*)d_in[2];
    const float* w_q    = (const float*)d_in[3];
    const float* w_k    = (const float*)d_in[4];
    const float* cvw    = (const float*)d_in[5];
    const float* cvb    = (const float*)d_in[6];
    const float* cow    = (const float*)d_in[7];
    const float* cob    = (const float*)d_in[8];
    const float* tk     = (const float*)d_in[9];
    const float* tv     = (const float*)d_in[10];
    float* out = (float*)d_out;

    static bool s_init = false;
    static cudaStream_t s1, s2;
    static cudaEvent_t ev0, ev1, ev2;
    if (!s_init) {
        cudaStreamCreateWithFlags(&s1, cudaStreamNonBlocking);
        cudaStreamCreateWithFlags(&s2, cudaStreamNonBlocking);
        cudaEventCreateWithFlags(&ev0, cudaEventDisableTiming);
        cudaEventCreateWithFlags(&ev1, cudaEventDisableTiming);
        cudaEventCreateWithFlags(&ev2, cudaEventDisableTiming);
        cudaFuncSetAttribute(conv_v_kernel, cudaFuncAttributeMaxDynamicSharedMemorySize, CV_SMEM_BYTES);
        cudaFuncSetAttribute(conv_o_kernel, cudaFuncAttributeMaxDynamicSharedMemorySize, CO_SMEM_BYTES);
        cudaFuncSetAttribute(gemm_splitk_q, cudaFuncAttributeMaxDynamicSharedMemorySize, GQ_SMEM_BYTES);
        s_init = true;
    }

    cudaStream_t origin = (cudaStream_t)0;
    cudaStreamCaptureStatus cs = cudaStreamCaptureStatusNone;
    cudaStreamIsCapturing(cudaStreamPerThread, &cs);
    if (cs == cudaStreamCaptureStatusActive) {
        origin = cudaStreamPerThread;
    } else {
        cudaStreamIsCapturing(cudaStreamLegacy, &cs);
        if (cs == cudaStreamCaptureStatusActive) origin = cudaStreamLegacy;
    }

    // fork side branches
    cudaEventRecord(ev0, origin);
    cudaStreamWaitEvent(s1, ev0, 0);
    cudaStreamWaitEvent(s2, ev0, 0);

    // branch 1: pool of k_antecedent
    pool_kernel<<<(NB * NS * 2048 + 255) / 256, 256, 0, s1>>>(k_ant, NB * NS, 1);
    cudaEventRecord(ev1, s1);

    // branch 2: conv weight fp16 fragment packing
    wtrans_kernel<<<(9 * 16 * 8 * 32 + 9 * 8 * 8 * 32 + 255) / 256, 256, 0, s2>>>(cvw, cow);
    cudaEventRecord(ev2, s2);

    // main chain: q path
    pool_kernel<<<(NB * 2048 + 255) / 256, 256, 0, origin>>>(inputs, NB, 0);
    gemm_splitk_q<<<dim3(8, KSLICES), 256, GQ_SMEM_BYTES, origin>>>(w_q);
    reduce_q<<<(NB * TKD + 255) / 256, 256, 0, origin>>>();
    p_kernel<<<dim3(NHD, 32), 256, 0, origin>>>(w_k);

    // join pool_k, then logits+softmax (ka and p each read once per CTA)
    cudaStreamWaitEvent(origin, ev1, 0);
    logits_kernel<<<dim3(NB, NHD), 256, 0, origin>>>(tk);

    // weighted V sum -> half
    vsum_kernel<<<dim3(32, NB), 256, 0, origin>>>(v_ant);

    // join wtrans, then convs (full-batch launches, 2 CTA/SM)
    cudaStreamWaitEvent(origin, ev2, 0);
    conv_v_kernel<<<dim3(NHD, NB), 256, CV_SMEM_BYTES, origin>>>(cvb, tv);
    conv_o_kernel<<<dim3(8, NB), 256, CO_SMEM_BYTES, origin>>>(cob, out);
}